// round 1
// baseline (speedup 1.0000x reference)
#include <cuda_runtime.h>
#include <math.h>

// Problem constants
#define NN 50000
#define EG 800000
// DIM = 128, H = 8, HD = 16

// ---------------- scratch (device globals; no runtime allocation) ----------
__device__ float  g_Q   [(size_t)NN * 128];
__device__ float  g_K   [(size_t)NN * 128];
__device__ float  g_V   [(size_t)NN * 128];
__device__ float  g_HA  [(size_t)NN * 128];   // h_attn
__device__ float  g_h1  [(size_t)NN * 128];
__device__ float  g_hidh[(size_t)NN * 256];
__device__ float  g_wV  [(size_t)NN * 128];
__device__ float  g_z   [(size_t)NN * 8];
__device__ float  g_EA  [(size_t)EG * 128];   // Ee, overwritten in-place with e_attn
__device__ float  g_e1  [(size_t)EG * 128];
__device__ float  g_hide[(size_t)EG * 256];
__device__ double g_sum [4 * 128];
__device__ double g_sq  [4 * 128];
__device__ float  g_bnsc[4 * 128];
__device__ float  g_bnsh[4 * 128];

// ---------------- zero accumulators ----------------------------------------
__global__ void k_zero() {
    size_t i = (size_t)blockIdx.x * blockDim.x + threadIdx.x;
    size_t stride = (size_t)gridDim.x * blockDim.x;
    for (size_t j = i; j < (size_t)NN * 128; j += stride) g_wV[j] = 0.f;
    for (size_t j = i; j < (size_t)NN * 8;   j += stride) g_z[j]  = 0.f;
    if (i < 512) { g_sum[i] = 0.0; g_sq[i] = 0.0; }
}

// ---------------- tiled fp32 GEMM: C = [res +] A@W + bias, optional relu ---
// BM=BN=64, BK=16, 256 threads, 4x4 per thread.
__global__ __launch_bounds__(256)
void k_gemm(const float* __restrict__ A, const float* __restrict__ W,
            const float* __restrict__ bias, const float* __restrict__ res,
            float* __restrict__ C, int M, int K, int Nc, int relu)
{
    __shared__ float As[16][64];   // [k][m]
    __shared__ float Ws[16][64];   // [k][n]
    const int m0 = blockIdx.y * 64;
    const int n0 = blockIdx.x * 64;
    const int tid = threadIdx.x;
    const int tx = tid & 15;       // n-quad
    const int ty = tid >> 4;       // m-quad
    float acc[4][4] = {};

    const int arow = tid >> 2;          // 0..63 rows of A tile
    const int ak4  = (tid & 3) * 4;     // k offset 0/4/8/12
    const int wrow = tid >> 4;          // 0..15 rows of W tile
    const int wn4  = (tid & 15) * 4;    // n offset

    for (int kk = 0; kk < K; kk += 16) {
        float4 av = make_float4(0.f, 0.f, 0.f, 0.f);
        int gm = m0 + arow;
        if (gm < M)
            av = *(const float4*)(A + (size_t)gm * K + kk + ak4);
        As[ak4 + 0][arow] = av.x;
        As[ak4 + 1][arow] = av.y;
        As[ak4 + 2][arow] = av.z;
        As[ak4 + 3][arow] = av.w;
        float4 wv = *(const float4*)(W + (size_t)(kk + wrow) * Nc + n0 + wn4);
        *(float4*)&Ws[wrow][wn4] = wv;
        __syncthreads();
        #pragma unroll
        for (int k = 0; k < 16; k++) {
            float4 a = *(const float4*)&As[k][ty * 4];
            float4 b = *(const float4*)&Ws[k][tx * 4];
            float av4[4] = {a.x, a.y, a.z, a.w};
            float bv4[4] = {b.x, b.y, b.z, b.w};
            #pragma unroll
            for (int i = 0; i < 4; i++)
                #pragma unroll
                for (int j = 0; j < 4; j++)
                    acc[i][j] += av4[i] * bv4[j];
        }
        __syncthreads();
    }

    float4 bv = *(const float4*)(bias + n0 + tx * 4);
    float bb[4] = {bv.x, bv.y, bv.z, bv.w};
    #pragma unroll
    for (int i = 0; i < 4; i++) {
        int gm = m0 + ty * 4 + i;
        if (gm >= M) continue;
        size_t base = (size_t)gm * Nc + n0 + tx * 4;
        float4 r = make_float4(0.f, 0.f, 0.f, 0.f);
        if (res) r = *(const float4*)(res + base);
        float rv[4] = {r.x, r.y, r.z, r.w};
        float out[4];
        #pragma unroll
        for (int j = 0; j < 4; j++) {
            float v = acc[i][j] + bb[j] + rv[j];
            if (relu) v = fmaxf(v, 0.f);
            out[j] = v;
        }
        *(float4*)(C + base) = make_float4(out[0], out[1], out[2], out[3]);
    }
}

// ---------------- edge kernel: score, e_attn (in place), s, segment sums ---
__global__ __launch_bounds__(256)
void k_edge(const int* __restrict__ src, const int* __restrict__ dst)
{
    const int t = threadIdx.x & 127;                     // 0..127 within edge
    const int e = blockIdx.x * 2 + (threadIdx.x >> 7);
    if (e >= EG) return;
    const int s = src[e];
    const int d = dst[e];
    // score = K[src]*Q[dst]*(1/sqrt(16)) * Ee
    float sc = g_K[(size_t)s * 128 + t] * g_Q[(size_t)d * 128 + t] * 0.25f
             * g_EA[(size_t)e * 128 + t];
    g_EA[(size_t)e * 128 + t] = sc;                      // e_attn
    // per-head sum over the 16 lanes of this head
    float sum = sc;
    #pragma unroll
    for (int off = 8; off; off >>= 1)
        sum += __shfl_xor_sync(0xffffffffu, sum, off, 16);
    sum = fminf(fmaxf(sum, -5.f), 5.f);
    float ss = __expf(sum);
    atomicAdd(&g_wV[(size_t)d * 128 + t], g_V[(size_t)s * 128 + t] * ss);
    if ((t & 15) == 0)
        atomicAdd(&g_z[(size_t)d * 8 + (t >> 4)], ss);
}

// ---------------- h_attn = wV / (z + 1e-6) ----------------------------------
__global__ void k_hattn()
{
    size_t i = (size_t)blockIdx.x * blockDim.x + threadIdx.x;
    if (i >= (size_t)NN * 128) return;
    int c = (int)(i & 127);
    size_t n = i >> 7;
    g_HA[i] = g_wV[i] / (g_z[n * 8 + (c >> 4)] + 1e-6f);
}

// ---------------- batch-norm: column stats / finalize / apply ---------------
__global__ __launch_bounds__(256)
void k_bn_reduce(const float* __restrict__ X, int M, int slot)
{
    int c  = threadIdx.x & 127;
    int r0 = blockIdx.x * 2 + (threadIdx.x >> 7);
    double s = 0.0, q = 0.0;
    for (int r = r0; r < M; r += gridDim.x * 2) {
        float v = X[(size_t)r * 128 + c];
        s += v;
        q += (double)v * v;
    }
    atomicAdd(&g_sum[slot * 128 + c], s);
    atomicAdd(&g_sq [slot * 128 + c], q);
}

__global__ void k_bn_finalize(int slot, float Mf,
                              const float* __restrict__ g, const float* __restrict__ b)
{
    int c = threadIdx.x;
    double mu  = g_sum[slot * 128 + c] / (double)Mf;
    double var = g_sq [slot * 128 + c] / (double)Mf - mu * mu;
    float sc = g[c] * rsqrtf((float)var + 1e-5f);
    g_bnsc[slot * 128 + c] = sc;
    g_bnsh[slot * 128 + c] = b[c] - (float)mu * sc;
}

__global__ __launch_bounds__(256)
void k_bn_apply(float* __restrict__ X, size_t M, int slot)
{
    size_t total4 = M * 32;  // float4 count per row-major [M,128]
    size_t i = (size_t)blockIdx.x * blockDim.x + threadIdx.x;
    size_t stride = (size_t)gridDim.x * blockDim.x;
    for (size_t j = i; j < total4; j += stride) {
        int c = (int)(j & 31) * 4;
        const float* sc = g_bnsc + slot * 128 + c;
        const float* sh = g_bnsh + slot * 128 + c;
        float4 v = ((float4*)X)[j];
        v.x = v.x * sc[0] + sh[0];
        v.y = v.y * sc[1] + sh[1];
        v.z = v.z * sc[2] + sh[2];
        v.w = v.w * sc[3] + sh[3];
        ((float4*)X)[j] = v;
    }
}

// ---------------- host orchestration ---------------------------------------
static void launch_gemm(const float* A, const float* W, const float* bias,
                        const float* res, float* C, int M, int K, int Nc, int relu)
{
    dim3 grid(Nc / 64, (M + 63) / 64);
    k_gemm<<<grid, 256>>>(A, W, bias, res, C, M, K, Nc, relu);
}

extern "C" void kernel_launch(void* const* d_in, const int* in_sizes, int n_in,
                              void* d_out, int out_size)
{
    const float* h   = (const float*)d_in[0];
    const float* e   = (const float*)d_in[1];
    const int*   src = (const int*)d_in[2];
    const int*   dst = (const int*)d_in[3];
    const float* WQ  = (const float*)d_in[4];   const float* bQ  = (const float*)d_in[5];
    const float* WK  = (const float*)d_in[6];   const float* bK  = (const float*)d_in[7];
    const float* WV  = (const float*)d_in[8];   const float* bV  = (const float*)d_in[9];
    const float* WE  = (const float*)d_in[10];  const float* bE  = (const float*)d_in[11];
    const float* WOh = (const float*)d_in[12];  const float* bOh = (const float*)d_in[13];
    const float* WOe = (const float*)d_in[14];  const float* bOe = (const float*)d_in[15];
    const float* Wh1 = (const float*)d_in[16];  const float* bh1 = (const float*)d_in[17];
    const float* Wh2 = (const float*)d_in[18];  const float* bh2 = (const float*)d_in[19];
    const float* We1 = (const float*)d_in[20];  const float* be1 = (const float*)d_in[21];
    const float* We2 = (const float*)d_in[22];  const float* be2 = (const float*)d_in[23];
    // setup_inputs dict order: g1h,g1e,g2h,g2e then b1h,b1e,b2h,b2e
    const float* g1h = (const float*)d_in[24];
    const float* g1e = (const float*)d_in[25];
    const float* g2h = (const float*)d_in[26];
    const float* g2e = (const float*)d_in[27];
    const float* b1h = (const float*)d_in[28];
    const float* b1e = (const float*)d_in[29];
    const float* b2h = (const float*)d_in[30];
    const float* b2e = (const float*)d_in[31];

    float *pQ, *pK, *pV, *pHA, *ph1, *phidh, *pEA, *pe1, *phide;
    cudaGetSymbolAddress((void**)&pQ,    g_Q);
    cudaGetSymbolAddress((void**)&pK,    g_K);
    cudaGetSymbolAddress((void**)&pV,    g_V);
    cudaGetSymbolAddress((void**)&pHA,   g_HA);
    cudaGetSymbolAddress((void**)&ph1,   g_h1);
    cudaGetSymbolAddress((void**)&phidh, g_hidh);
    cudaGetSymbolAddress((void**)&pEA,   g_EA);
    cudaGetSymbolAddress((void**)&pe1,   g_e1);
    cudaGetSymbolAddress((void**)&phide, g_hide);

    float* out_h = (float*)d_out;                       // [NN,128]
    float* out_e = (float*)d_out + (size_t)NN * 128;    // [EG,128]

    // 0) zero accumulators + BN stats
    k_zero<<<4096, 256>>>();

    // 1) projections
    launch_gemm(h, WQ, bQ, nullptr, pQ,  NN, 128, 128, 0);
    launch_gemm(h, WK, bK, nullptr, pK,  NN, 128, 128, 0);
    launch_gemm(h, WV, bV, nullptr, pV,  NN, 128, 128, 0);
    launch_gemm(e, WE, bE, nullptr, pEA, EG, 128, 128, 0);

    // 2) edge scores + softmax-ish weights + segment sums (atomics)
    k_edge<<<EG / 2, 256>>>(src, dst);

    // 3) h_attn
    k_hattn<<<(NN * 128 + 255) / 256, 256>>>();

    // 4) O projections with residual
    launch_gemm(pHA, WOh, bOh, h, ph1, NN, 128, 128, 0);
    launch_gemm(pEA, WOe, bOe, e, pe1, EG, 128, 128, 0);

    // 5) BN #1
    k_bn_reduce<<<1024, 256>>>(ph1, NN, 0);
    k_bn_finalize<<<1, 128>>>(0, (float)NN, g1h, b1h);
    k_bn_apply<<<12800, 256>>>(ph1, (size_t)NN, 0);
    k_bn_reduce<<<2048, 256>>>(pe1, EG, 1);
    k_bn_finalize<<<1, 128>>>(1, (float)EG, g1e, b1e);
    k_bn_apply<<<100000, 256>>>(pe1, (size_t)EG, 1);

    // 6) FFNs (dim -> 2*dim -> dim) with residual
    launch_gemm(ph1,   Wh1, bh1, nullptr, phidh, NN, 128, 256, 1);
    launch_gemm(phidh, Wh2, bh2, ph1,     out_h, NN, 256, 128, 0);
    launch_gemm(pe1,   We1, be1, nullptr, phide, EG, 128, 256, 1);
    launch_gemm(phide, We2, be2, pe1,     out_e, EG, 256, 128, 0);

    // 7) BN #2 (in place on the output buffer)
    k_bn_reduce<<<1024, 256>>>(out_h, NN, 2);
    k_bn_finalize<<<1, 128>>>(2, (float)NN, g2h, b2h);
    k_bn_apply<<<12800, 256>>>(out_h, (size_t)NN, 2);
    k_bn_reduce<<<2048, 256>>>(out_e, EG, 3);
    k_bn_finalize<<<1, 128>>>(3, (float)EG, g2e, b2e);
    k_bn_apply<<<100000, 256>>>(out_e, (size_t)EG, 3);
}

// round 3
// speedup vs baseline: 1.4271x; 1.4271x over previous
#include <cuda_runtime.h>
#include <cuda_bf16.h>
#include <cstdint>
#include <math.h>

// Problem constants
#define NN 50000
#define EG 800000
// DIM = 128, H = 8, HD = 16

// ---------------- scratch (device globals; no runtime allocation) ----------
__device__ float  g_Q   [(size_t)NN * 128];
__device__ float  g_K   [(size_t)NN * 128];
__device__ float  g_V   [(size_t)NN * 128];
__device__ float  g_HA  [(size_t)NN * 128];   // h_attn
__device__ float  g_h1  [(size_t)NN * 128];
__device__ float  g_hidh[(size_t)NN * 256];
__device__ float  g_wV  [(size_t)NN * 128];
__device__ float  g_z   [(size_t)NN * 8];
__device__ float  g_EA  [(size_t)EG * 128];   // Ee, overwritten in-place with e_attn
__device__ float  g_e1  [(size_t)EG * 128];
__device__ float  g_hide[(size_t)EG * 256];
__device__ double g_sum [4 * 128];
__device__ double g_sq  [4 * 128];
__device__ float  g_bnsc[4 * 128];
__device__ float  g_bnsh[4 * 128];

// ---------------- zero accumulators ----------------------------------------
__global__ void k_zero() {
    size_t i = (size_t)blockIdx.x * blockDim.x + threadIdx.x;
    size_t stride = (size_t)gridDim.x * blockDim.x;
    for (size_t j = i; j < (size_t)NN * 128; j += stride) g_wV[j] = 0.f;
    for (size_t j = i; j < (size_t)NN * 8;   j += stride) g_z[j]  = 0.f;
    if (i < 512) { g_sum[i] = 0.0; g_sq[i] = 0.0; }
}

// ============================================================================
// mma.sync bf16 helpers (family-portable PTX; no 'a'-gated instructions)
// ============================================================================
__device__ __forceinline__ uint32_t smem_u32(const void* p) {
    uint32_t a;
    asm("{ .reg .u64 t; cvta.to.shared.u64 t, %1; cvt.u32.u64 %0, t; }"
        : "=r"(a) : "l"(p));
    return a;
}

__device__ __forceinline__ void ldsm_x4(uint32_t addr, uint32_t* r) {
    asm volatile("ldmatrix.sync.aligned.m8n8.x4.shared.b16 {%0,%1,%2,%3}, [%4];"
        : "=r"(r[0]), "=r"(r[1]), "=r"(r[2]), "=r"(r[3]) : "r"(addr));
}

__device__ __forceinline__ void mma_bf16(float* acc, const uint32_t* a, const uint32_t* b) {
    asm volatile(
        "mma.sync.aligned.m16n8k16.row.col.f32.bf16.bf16.f32 "
        "{%0,%1,%2,%3},{%4,%5,%6,%7},{%8,%9},{%0,%1,%2,%3};"
        : "+f"(acc[0]), "+f"(acc[1]), "+f"(acc[2]), "+f"(acc[3])
        : "r"(a[0]), "r"(a[1]), "r"(a[2]), "r"(a[3]), "r"(b[0]), "r"(b[1]));
}

// fp32 -> (bf16 hi, bf16 lo-residual), two elements packed into b32 each
__device__ __forceinline__ void split_pair(float x0, float x1, uint32_t& hi, uint32_t& lo)
{
    __nv_bfloat162 h = __floats2bfloat162_rn(x0, x1);
    float r0 = x0 - __bfloat162float(__low2bfloat16(h));
    float r1 = x1 - __bfloat162float(__high2bfloat16(h));
    __nv_bfloat162 l = __floats2bfloat162_rn(r0, r1);
    hi = *reinterpret_cast<uint32_t*>(&h);
    lo = *reinterpret_cast<uint32_t*>(&l);
}

// ============================================================================
// HMMA bf16 3-split GEMM: C = [res +] A@W + bias, optional relu
// A [M,K] fp32 row-major, W [K,Nc] fp32 row-major, C [M,Nc] fp32.
// Shapes used: (K,Nc) in {(128,128), (128,256), (256,128)}.
// 256 threads = 8 warps (2 M x 4 N), block tile 128 x min(Nc,128),
// warp tile 64x32, mma m16n8k16, 3 products per tile pair (hi*hi, hi*lo, lo*hi).
//
// SMEM (dynamic):
//   A_hi [128][AS=136] bf16, A_lo same        (2 x 34816 B)
//   B_hi [Nc][BS=K+8] bf16, B_lo same         (2 x Nc*BS*2 B)
// ============================================================================
#define AS 136

__global__ __launch_bounds__(256)
void k_mmgemm(const float* __restrict__ A, const float* __restrict__ W,
              const float* __restrict__ bias, const float* __restrict__ res,
              float* __restrict__ C, int M, int K, int Nc, int relu)
{
    extern __shared__ char smem[];
    const int BS = K + 8;
    const uint32_t sbase  = smem_u32(smem);
    const uint32_t A_HI   = 0;
    const uint32_t A_LO   = 128 * AS * 2;
    const uint32_t B_HI   = 2 * 128 * AS * 2;
    const uint32_t B_LO   = B_HI + (uint32_t)Nc * (uint32_t)BS * 2u;

    const int tid  = threadIdx.x;
    const int lane = tid & 31;
    const int wid  = tid >> 5;
    const int wm   = wid >> 2;          // 0..1  (M)
    const int wn   = wid & 3;           // 0..3  (N)

    // ---- load W once per CTA: fp32 [K][Nc] -> bf16 hi/lo at [n][k]
    {
        const int tot = (K >> 2) * Nc;
        for (int i = tid; i < tot; i += 256) {
            int n  = i % Nc;
            int k4 = (i / Nc) << 2;
            size_t gb = (size_t)k4 * Nc + n;
            float x0 = W[gb];
            float x1 = W[gb + Nc];
            float x2 = W[gb + 2 * (size_t)Nc];
            float x3 = W[gb + 3 * (size_t)Nc];
            uint32_t h01, l01, h23, l23;
            split_pair(x0, x1, h01, l01);
            split_pair(x2, x3, h23, l23);
            uint32_t off = ((uint32_t)n * BS + k4) * 2u;
            *(uint2*)(smem + B_HI + off) = make_uint2(h01, h23);
            *(uint2*)(smem + B_LO + off) = make_uint2(l01, l23);
        }
    }

    const int KC = K >> 7;   // 1 or 2
    const int NH = Nc >> 7;  // 1 or 2
    const int tiles = (M + 127) >> 7;

    // ldmatrix lane-address components
    const int a_row = (lane & 15);            // + mbase
    const int a_k   = (lane >> 4) << 3;       // 0 / 8
    const int b_row = (lane & 7) + ((lane >> 4) << 3);  // + nbase
    const int b_k   = ((lane >> 3) & 1) << 3; // 0 / 8 / 0 / 8

    for (int t = blockIdx.x; t < tiles; t += gridDim.x) {
        const int m0 = t << 7;

        if (KC == 1) {
            // single K chunk: load A once, loop N halves
            __syncthreads();
            for (int i = tid; i < 4096; i += 256) {
                int r  = i >> 5;
                int c4 = (i & 31) << 2;
                float4 v = make_float4(0.f, 0.f, 0.f, 0.f);
                int gm = m0 + r;
                if (gm < M) v = *(const float4*)(A + (size_t)gm * K + c4);
                uint32_t h01, l01, h23, l23;
                split_pair(v.x, v.y, h01, l01);
                split_pair(v.z, v.w, h23, l23);
                uint32_t off = ((uint32_t)r * AS + c4) * 2u;
                *(uint2*)(smem + A_HI + off) = make_uint2(h01, h23);
                *(uint2*)(smem + A_LO + off) = make_uint2(l01, l23);
            }
            __syncthreads();

            for (int nh = 0; nh < NH; nh++) {
                float acc[4][4][4] = {};
                const int bn = nh * 128 + wn * 32;
                #pragma unroll
                for (int ks = 0; ks < 8; ks++) {
                    const int ka = (ks << 4);
                    uint32_t ah[4][4], al[4][4], bh[4][2], bl[4][2];
                    #pragma unroll
                    for (int mt = 0; mt < 4; mt++) {
                        uint32_t roff = ((uint32_t)(wm * 64 + mt * 16 + a_row) * AS
                                         + (ka + a_k)) * 2u;
                        ldsm_x4(sbase + A_HI + roff, ah[mt]);
                        ldsm_x4(sbase + A_LO + roff, al[mt]);
                    }
                    #pragma unroll
                    for (int np = 0; np < 2; np++) {      // n-tile pairs
                        uint32_t roff = ((uint32_t)(bn + np * 16 + b_row) * BS
                                         + (ka + b_k)) * 2u;
                        uint32_t rh[4], rl[4];
                        ldsm_x4(sbase + B_HI + roff, rh);
                        ldsm_x4(sbase + B_LO + roff, rl);
                        bh[np*2][0] = rh[0]; bh[np*2][1] = rh[1];
                        bh[np*2+1][0] = rh[2]; bh[np*2+1][1] = rh[3];
                        bl[np*2][0] = rl[0]; bl[np*2][1] = rl[1];
                        bl[np*2+1][0] = rl[2]; bl[np*2+1][1] = rl[3];
                    }
                    #pragma unroll
                    for (int mt = 0; mt < 4; mt++)
                        #pragma unroll
                        for (int nt = 0; nt < 4; nt++) {
                            mma_bf16(acc[mt][nt], ah[mt], bh[nt]);
                            mma_bf16(acc[mt][nt], ah[mt], bl[nt]);
                            mma_bf16(acc[mt][nt], al[mt], bh[nt]);
                        }
                }
                // epilogue
                const int g  = lane >> 2;
                const int t2 = (lane & 3) << 1;
                #pragma unroll
                for (int mt = 0; mt < 4; mt++) {
                    int r0 = m0 + wm * 64 + mt * 16 + g;
                    #pragma unroll
                    for (int nt = 0; nt < 4; nt++) {
                        int c0 = bn + nt * 8 + t2;
                        float2 bv = *(const float2*)(bias + c0);
                        if (r0 < M) {
                            size_t o = (size_t)r0 * Nc + c0;
                            float2 v = make_float2(acc[mt][nt][0] + bv.x,
                                                   acc[mt][nt][1] + bv.y);
                            if (res) { float2 rv = *(const float2*)(res + o);
                                       v.x += rv.x; v.y += rv.y; }
                            if (relu) { v.x = fmaxf(v.x, 0.f); v.y = fmaxf(v.y, 0.f); }
                            *(float2*)(C + o) = v;
                        }
                        if (r0 + 8 < M) {
                            size_t o = (size_t)(r0 + 8) * Nc + c0;
                            float2 v = make_float2(acc[mt][nt][2] + bv.x,
                                                   acc[mt][nt][3] + bv.y);
                            if (res) { float2 rv = *(const float2*)(res + o);
                                       v.x += rv.x; v.y += rv.y; }
                            if (relu) { v.x = fmaxf(v.x, 0.f); v.y = fmaxf(v.y, 0.f); }
                            *(float2*)(C + o) = v;
                        }
                    }
                }
            }
        } else {
            // KC == 2 (K=256, Nc=128): accumulate across two A chunks
            float acc[4][4][4] = {};
            const int bn = wn * 32;
            for (int kc = 0; kc < 2; kc++) {
                __syncthreads();
                for (int i = tid; i < 4096; i += 256) {
                    int r  = i >> 5;
                    int c4 = (i & 31) << 2;
                    float4 v = make_float4(0.f, 0.f, 0.f, 0.f);
                    int gm = m0 + r;
                    if (gm < M) v = *(const float4*)(A + (size_t)gm * K + (kc << 7) + c4);
                    uint32_t h01, l01, h23, l23;
                    split_pair(v.x, v.y, h01, l01);
                    split_pair(v.z, v.w, h23, l23);
                    uint32_t off = ((uint32_t)r * AS + c4) * 2u;
                    *(uint2*)(smem + A_HI + off) = make_uint2(h01, h23);
                    *(uint2*)(smem + A_LO + off) = make_uint2(l01, l23);
                }
                __syncthreads();
                #pragma unroll
                for (int ks = 0; ks < 8; ks++) {
                    const int ka = (ks << 4);
                    const int kb = (kc << 7) + ka;
                    uint32_t ah[4][4], al[4][4], bh[4][2], bl[4][2];
                    #pragma unroll
                    for (int mt = 0; mt < 4; mt++) {
                        uint32_t roff = ((uint32_t)(wm * 64 + mt * 16 + a_row) * AS
                                         + (ka + a_k)) * 2u;
                        ldsm_x4(sbase + A_HI + roff, ah[mt]);
                        ldsm_x4(sbase + A_LO + roff, al[mt]);
                    }
                    #pragma unroll
                    for (int np = 0; np < 2; np++) {
                        uint32_t roff = ((uint32_t)(bn + np * 16 + b_row) * BS
                                         + (kb + b_k)) * 2u;
                        uint32_t rh[4], rl[4];
                        ldsm_x4(sbase + B_HI + roff, rh);
                        ldsm_x4(sbase + B_LO + roff, rl);
                        bh[np*2][0] = rh[0]; bh[np*2][1] = rh[1];
                        bh[np*2+1][0] = rh[2]; bh[np*2+1][1] = rh[3];
                        bl[np*2][0] = rl[0]; bl[np*2][1] = rl[1];
                        bl[np*2+1][0] = rl[2]; bl[np*2+1][1] = rl[3];
                    }
                    #pragma unroll
                    for (int mt = 0; mt < 4; mt++)
                        #pragma unroll
                        for (int nt = 0; nt < 4; nt++) {
                            mma_bf16(acc[mt][nt], ah[mt], bh[nt]);
                            mma_bf16(acc[mt][nt], ah[mt], bl[nt]);
                            mma_bf16(acc[mt][nt], al[mt], bh[nt]);
                        }
                }
            }
            const int g  = lane >> 2;
            const int t2 = (lane & 3) << 1;
            #pragma unroll
            for (int mt = 0; mt < 4; mt++) {
                int r0 = m0 + wm * 64 + mt * 16 + g;
                #pragma unroll
                for (int nt = 0; nt < 4; nt++) {
                    int c0 = bn + nt * 8 + t2;
                    float2 bv = *(const float2*)(bias + c0);
                    if (r0 < M) {
                        size_t o = (size_t)r0 * Nc + c0;
                        float2 v = make_float2(acc[mt][nt][0] + bv.x,
                                               acc[mt][nt][1] + bv.y);
                        if (res) { float2 rv = *(const float2*)(res + o);
                                   v.x += rv.x; v.y += rv.y; }
                        if (relu) { v.x = fmaxf(v.x, 0.f); v.y = fmaxf(v.y, 0.f); }
                        *(float2*)(C + o) = v;
                    }
                    if (r0 + 8 < M) {
                        size_t o = (size_t)(r0 + 8) * Nc + c0;
                        float2 v = make_float2(acc[mt][nt][2] + bv.x,
                                               acc[mt][nt][3] + bv.y);
                        if (res) { float2 rv = *(const float2*)(res + o);
                                   v.x += rv.x; v.y += rv.y; }
                        if (relu) { v.x = fmaxf(v.x, 0.f); v.y = fmaxf(v.y, 0.f); }
                        *(float2*)(C + o) = v;
                    }
                }
            }
        }
    }
}

// ---------------- edge kernel: score, e_attn (in place), s, segment sums ---
__global__ __launch_bounds__(256)
void k_edge(const int* __restrict__ src, const int* __restrict__ dst)
{
    const int t = threadIdx.x & 127;
    const int e = blockIdx.x * 2 + (threadIdx.x >> 7);
    if (e >= EG) return;
    const int s = src[e];
    const int d = dst[e];
    float sc = g_K[(size_t)s * 128 + t] * g_Q[(size_t)d * 128 + t] * 0.25f
             * g_EA[(size_t)e * 128 + t];
    g_EA[(size_t)e * 128 + t] = sc;
    float sum = sc;
    #pragma unroll
    for (int off = 8; off; off >>= 1)
        sum += __shfl_xor_sync(0xffffffffu, sum, off, 16);
    sum = fminf(fmaxf(sum, -5.f), 5.f);
    float ss = __expf(sum);
    atomicAdd(&g_wV[(size_t)d * 128 + t], g_V[(size_t)s * 128 + t] * ss);
    if ((t & 15) == 0)
        atomicAdd(&g_z[(size_t)d * 8 + (t >> 4)], ss);
}

// ---------------- h_attn = wV / (z + 1e-6) ----------------------------------
__global__ void k_hattn()
{
    size_t i = (size_t)blockIdx.x * blockDim.x + threadIdx.x;
    if (i >= (size_t)NN * 128) return;
    int c = (int)(i & 127);
    size_t n = i >> 7;
    g_HA[i] = g_wV[i] / (g_z[n * 8 + (c >> 4)] + 1e-6f);
}

// ---------------- batch-norm ------------------------------------------------
__global__ __launch_bounds__(256)
void k_bn_reduce(const float* __restrict__ X, int M, int slot)
{
    int c  = threadIdx.x & 127;
    int r0 = blockIdx.x * 2 + (threadIdx.x >> 7);
    double s = 0.0, q = 0.0;
    for (int r = r0; r < M; r += gridDim.x * 2) {
        float v = X[(size_t)r * 128 + c];
        s += v;
        q += (double)v * v;
    }
    atomicAdd(&g_sum[slot * 128 + c], s);
    atomicAdd(&g_sq [slot * 128 + c], q);
}

__global__ void k_bn_finalize(int slot, float Mf,
                              const float* __restrict__ g, const float* __restrict__ b)
{
    int c = threadIdx.x;
    double mu  = g_sum[slot * 128 + c] / (double)Mf;
    double var = g_sq [slot * 128 + c] / (double)Mf - mu * mu;
    float sc = g[c] * rsqrtf((float)var + 1e-5f);
    g_bnsc[slot * 128 + c] = sc;
    g_bnsh[slot * 128 + c] = b[c] - (float)mu * sc;
}

__global__ __launch_bounds__(256)
void k_bn_apply(float* __restrict__ X, size_t M, int slot)
{
    size_t total4 = M * 32;
    size_t i = (size_t)blockIdx.x * blockDim.x + threadIdx.x;
    size_t stride = (size_t)gridDim.x * blockDim.x;
    for (size_t j = i; j < total4; j += stride) {
        int c = (int)(j & 31) * 4;
        const float* sc = g_bnsc + slot * 128 + c;
        const float* sh = g_bnsh + slot * 128 + c;
        float4 v = ((float4*)X)[j];
        v.x = v.x * sc[0] + sh[0];
        v.y = v.y * sc[1] + sh[1];
        v.z = v.z * sc[2] + sh[2];
        v.w = v.w * sc[3] + sh[3];
        ((float4*)X)[j] = v;
    }
}

// ---------------- host orchestration ---------------------------------------
static void mm_gemm(const float* A, const float* W, const float* bias,
                    const float* res, float* C, int M, int K, int Nc, int relu)
{
    int tiles = (M + 127) / 128;
    int grid = tiles < 148 ? tiles : 148;
    size_t smem = 2 * 128 * AS * 2 + (size_t)Nc * (K + 8) * 2 * 2;
    k_mmgemm<<<grid, 256, smem>>>(A, W, bias, res, C, M, K, Nc, relu);
}

extern "C" void kernel_launch(void* const* d_in, const int* in_sizes, int n_in,
                              void* d_out, int out_size)
{
    const float* h   = (const float*)d_in[0];
    const float* e   = (const float*)d_in[1];
    const int*   src = (const int*)d_in[2];
    const int*   dst = (const int*)d_in[3];
    const float* WQ  = (const float*)d_in[4];   const float* bQ  = (const float*)d_in[5];
    const float* WK  = (const float*)d_in[6];   const float* bK  = (const float*)d_in[7];
    const float* WV  = (const float*)d_in[8];   const float* bV  = (const float*)d_in[9];
    const float* WE  = (const float*)d_in[10];  const float* bE  = (const float*)d_in[11];
    const float* WOh = (const float*)d_in[12];  const float* bOh = (const float*)d_in[13];
    const float* WOe = (const float*)d_in[14];  const float* bOe = (const float*)d_in[15];
    const float* Wh1 = (const float*)d_in[16];  const float* bh1 = (const float*)d_in[17];
    const float* Wh2 = (const float*)d_in[18];  const float* bh2 = (const float*)d_in[19];
    const float* We1 = (const float*)d_in[20];  const float* be1 = (const float*)d_in[21];
    const float* We2 = (const float*)d_in[22];  const float* be2 = (const float*)d_in[23];
    const float* g1h = (const float*)d_in[24];
    const float* g1e = (const float*)d_in[25];
    const float* g2h = (const float*)d_in[26];
    const float* g2e = (const float*)d_in[27];
    const float* b1h = (const float*)d_in[28];
    const float* b1e = (const float*)d_in[29];
    const float* b2h = (const float*)d_in[30];
    const float* b2e = (const float*)d_in[31];

    float *pQ, *pK, *pV, *pHA, *ph1, *phidh, *pEA, *pe1, *phide;
    cudaGetSymbolAddress((void**)&pQ,    g_Q);
    cudaGetSymbolAddress((void**)&pK,    g_K);
    cudaGetSymbolAddress((void**)&pV,    g_V);
    cudaGetSymbolAddress((void**)&pHA,   g_HA);
    cudaGetSymbolAddress((void**)&ph1,   g_h1);
    cudaGetSymbolAddress((void**)&phidh, g_hidh);
    cudaGetSymbolAddress((void**)&pEA,   g_EA);
    cudaGetSymbolAddress((void**)&pe1,   g_e1);
    cudaGetSymbolAddress((void**)&phide, g_hide);

    // max smem: Nc=256,K=128 -> 69632 + 256*136*4 = 208896 bytes
    cudaFuncSetAttribute(k_mmgemm, cudaFuncAttributeMaxDynamicSharedMemorySize, 209920);

    float* out_h = (float*)d_out;                       // [NN,128]
    float* out_e = (float*)d_out + (size_t)NN * 128;    // [EG,128]

    // 0) zero accumulators + BN stats
    k_zero<<<4096, 256>>>();

    // 1) projections (HMMA bf16-split GEMMs)
    mm_gemm(h, WQ, bQ, nullptr, pQ,  NN, 128, 128, 0);
    mm_gemm(h, WK, bK, nullptr, pK,  NN, 128, 128, 0);
    mm_gemm(h, WV, bV, nullptr, pV,  NN, 128, 128, 0);
    mm_gemm(e, WE, bE, nullptr, pEA, EG, 128, 128, 0);

    // 2) edge scores + attention weights + segment sums (atomics)
    k_edge<<<EG / 2, 256>>>(src, dst);

    // 3) h_attn
    k_hattn<<<(NN * 128 + 255) / 256, 256>>>();

    // 4) O projections with residual
    mm_gemm(pHA, WOh, bOh, h, ph1, NN, 128, 128, 0);
    mm_gemm(pEA, WOe, bOe, e, pe1, EG, 128, 128, 0);

    // 5) BN #1
    k_bn_reduce<<<1024, 256>>>(ph1, NN, 0);
    k_bn_finalize<<<1, 128>>>(0, (float)NN, g1h, b1h);
    k_bn_apply<<<12800, 256>>>(ph1, (size_t)NN, 0);
    k_bn_reduce<<<2048, 256>>>(pe1, EG, 1);
    k_bn_finalize<<<1, 128>>>(1, (float)EG, g1e, b1e);
    k_bn_apply<<<100000, 256>>>(pe1, (size_t)EG, 1);

    // 6) FFNs (dim -> 2*dim -> dim) with residual
    mm_gemm(ph1,   Wh1, bh1, nullptr, phidh, NN, 128, 256, 1);
    mm_gemm(phidh, Wh2, bh2, ph1,     out_h, NN, 256, 128, 0);
    mm_gemm(pe1,   We1, be1, nullptr, phide, EG, 128, 256, 1);
    mm_gemm(phide, We2, be2, pe1,     out_e, EG, 256, 128, 0);

    // 7) BN #2 (in place on the output buffer)
    k_bn_reduce<<<1024, 256>>>(out_h, NN, 2);
    k_bn_finalize<<<1, 128>>>(2, (float)NN, g2h, b2h);
    k_bn_apply<<<12800, 256>>>(out_h, (size_t)NN, 2);
    k_bn_reduce<<<2048, 256>>>(out_e, EG, 3);
    k_bn_finalize<<<1, 128>>>(3, (float)EG, g2e, b2e);
    k_bn_apply<<<100000, 256>>>(out_e, (size_t)EG, 3);
}

// round 4
// speedup vs baseline: 1.6349x; 1.1456x over previous
#include <cuda_runtime.h>
#include <cuda_bf16.h>
#include <cstdint>
#include <math.h>

// Problem constants
#define NN 50000
#define EG 800000
// DIM = 128, H = 8, HD = 16

// ---------------- scratch (device globals; no runtime allocation) ----------
__device__ float  g_Q   [(size_t)NN * 128];
__device__ float  g_K   [(size_t)NN * 128];
__device__ float  g_V   [(size_t)NN * 128];
__device__ float  g_HA  [(size_t)NN * 128];   // h_attn
__device__ float  g_h1  [(size_t)NN * 128];
__device__ float  g_hidh[(size_t)NN * 256];
__device__ float  g_wV  [(size_t)NN * 128];
__device__ float  g_z   [(size_t)NN * 8];
__device__ float  g_EA  [(size_t)EG * 128];   // Ee, overwritten in-place with e_attn
__device__ float  g_e1  [(size_t)EG * 128];
__device__ float  g_hide[(size_t)EG * 256];
__device__ double g_sum [4 * 128];
__device__ double g_sq  [4 * 128];
__device__ float  g_bnsc[4 * 128];
__device__ float  g_bnsh[4 * 128];

// ---------------- zero accumulators ----------------------------------------
__global__ void k_zero() {
    size_t i = (size_t)blockIdx.x * blockDim.x + threadIdx.x;
    size_t stride = (size_t)gridDim.x * blockDim.x;
    for (size_t j = i; j < (size_t)NN * 128; j += stride) g_wV[j] = 0.f;
    for (size_t j = i; j < (size_t)NN * 8;   j += stride) g_z[j]  = 0.f;
    if (i < 512) { g_sum[i] = 0.0; g_sq[i] = 0.0; }
}

// ============================================================================
// mma.sync bf16 helpers (family-portable PTX)
// ============================================================================
__device__ __forceinline__ uint32_t smem_u32(const void* p) {
    uint32_t a;
    asm("{ .reg .u64 t; cvta.to.shared.u64 t, %1; cvt.u32.u64 %0, t; }"
        : "=r"(a) : "l"(p));
    return a;
}

__device__ __forceinline__ void ldsm_x4(uint32_t addr, uint32_t* r) {
    asm volatile("ldmatrix.sync.aligned.m8n8.x4.shared.b16 {%0,%1,%2,%3}, [%4];"
        : "=r"(r[0]), "=r"(r[1]), "=r"(r[2]), "=r"(r[3]) : "r"(addr));
}

__device__ __forceinline__ void mma_bf16(float* acc, const uint32_t* a, const uint32_t* b) {
    asm volatile(
        "mma.sync.aligned.m16n8k16.row.col.f32.bf16.bf16.f32 "
        "{%0,%1,%2,%3},{%4,%5,%6,%7},{%8,%9},{%0,%1,%2,%3};"
        : "+f"(acc[0]), "+f"(acc[1]), "+f"(acc[2]), "+f"(acc[3])
        : "r"(a[0]), "r"(a[1]), "r"(a[2]), "r"(a[3]), "r"(b[0]), "r"(b[1]));
}

__device__ __forceinline__ void split_pair(float x0, float x1, uint32_t& hi, uint32_t& lo)
{
    __nv_bfloat162 h = __floats2bfloat162_rn(x0, x1);
    float r0 = x0 - __bfloat162float(__low2bfloat16(h));
    float r1 = x1 - __bfloat162float(__high2bfloat16(h));
    __nv_bfloat162 l = __floats2bfloat162_rn(r0, r1);
    hi = *reinterpret_cast<uint32_t*>(&h);
    lo = *reinterpret_cast<uint32_t*>(&l);
}

// ============================================================================
// Pipelined HMMA bf16 3-split GEMM, N-tile fixed at 128 columns.
//   C[:, :128] = [resOp(res) +] Aop(A) @ W[:, :128] + bias, optional relu
// KC = K/64 (2 or 4). A [M,K] fp32, W row-major with leading dim Wld,
// C/res with leading dim Cld. Optional per-k affine on A (Asc/Ash) and
// per-col affine on res (Rsc/Rsh) for fused batch-norm.
//
// 256 threads = 8 warps (2 wm x 4 wn), warp tile 64x32, M-tile 128.
// A double-buffered in smem as bf16 hi/lo, k-chunks of 64, register prefetch.
//
// SMEM: A: 2 bufs x (hi+lo) x [128][72] bf16 = 73728 B
//       B: (hi+lo) x [128][K+8] bf16
// ============================================================================
#define A_CH_B 18432          // one split of one A buffer: 128*72*2
#define A_BUF_B 36864         // hi+lo of one buffer
#define B_BASE 73728

template<int KC>
__global__ __launch_bounds__(256)
void k_mmgemm(const float* __restrict__ A, const float* __restrict__ W,
              const float* __restrict__ bias, const float* __restrict__ res,
              float* __restrict__ C, int M, int Wld, int Cld, int relu,
              const float* __restrict__ Asc, const float* __restrict__ Ash,
              const float* __restrict__ Rsc, const float* __restrict__ Rsh)
{
    extern __shared__ char smem[];
    constexpr int K  = KC * 64;
    constexpr int BS = K + 8;
    constexpr uint32_t BB = 128u * BS * 2u;   // bytes of one B split
    const uint32_t sbase = smem_u32(smem);

    const int tid  = threadIdx.x;
    const int lane = tid & 31;
    const int wid  = tid >> 5;
    const int wm   = wid >> 2;          // 0..1
    const int wn   = wid & 3;           // 0..3

    // ---- load W[:, 0:128] once: fp32 -> bf16 hi/lo at [n][k]
    {
        #pragma unroll
        for (int i = tid; i < (K >> 2) * 128; i += 256) {
            int n  = i & 127;
            int k4 = (i >> 7) << 2;
            const float* wp = W + (size_t)k4 * Wld + n;
            float x0 = wp[0];
            float x1 = wp[Wld];
            float x2 = wp[2 * Wld];
            float x3 = wp[3 * Wld];
            uint32_t h01, l01, h23, l23;
            split_pair(x0, x1, h01, l01);
            split_pair(x2, x3, h23, l23);
            uint32_t off = ((uint32_t)n * BS + k4) * 2u;
            *(uint2*)(smem + B_BASE + off)      = make_uint2(h01, h23);
            *(uint2*)(smem + B_BASE + BB + off) = make_uint2(l01, l23);
        }
    }

    const int tiles = (M + 127) >> 7;

    // ldmatrix lane-address components
    const int a_row = (lane & 15);
    const int a_k   = (lane >> 4) << 3;
    const int b_row = (lane & 7) + ((lane >> 4) << 3);
    const int b_k   = ((lane >> 3) & 1) << 3;

    float4 pf[8];
    int t = blockIdx.x;
    // prefetch first chunk
    if (t < tiles) {
        int m0 = t << 7;
        #pragma unroll
        for (int j = 0; j < 8; j++) {
            int idx = tid + (j << 8);
            int gm = m0 + (idx >> 4); if (gm > M - 1) gm = M - 1;
            pf[j] = *(const float4*)(A + (size_t)gm * K + ((idx & 15) << 2));
        }
    }
    int buf = 0;

    for (; t < tiles; t += gridDim.x) {
        const int m0 = t << 7;
        float acc[4][4][4] = {};
        #pragma unroll
        for (int kc = 0; kc < KC; kc++) {
            const int kb = kc << 6;
            // ---- convert + store current prefetched chunk into buf
            {
                char* ah_base = smem + buf * A_BUF_B;
                #pragma unroll
                for (int j = 0; j < 8; j++) {
                    int idx = tid + (j << 8);
                    int row = idx >> 4;
                    int c4  = (idx & 15) << 2;
                    float4 v = pf[j];
                    if (Asc) {
                        float4 sc = *(const float4*)(Asc + kb + c4);
                        float4 sh = *(const float4*)(Ash + kb + c4);
                        v.x = v.x * sc.x + sh.x;
                        v.y = v.y * sc.y + sh.y;
                        v.z = v.z * sc.z + sh.z;
                        v.w = v.w * sc.w + sh.w;
                    }
                    uint32_t h01, l01, h23, l23;
                    split_pair(v.x, v.y, h01, l01);
                    split_pair(v.z, v.w, h23, l23);
                    uint32_t off = ((uint32_t)row * 72 + c4) * 2u;
                    *(uint2*)(ah_base + off)          = make_uint2(h01, h23);
                    *(uint2*)(ah_base + A_CH_B + off) = make_uint2(l01, l23);
                }
            }
            __syncthreads();
            // ---- prefetch next chunk (overlaps with MMA below)
            {
                int kc2 = kc + 1, t2 = t;
                if (kc2 == KC) { kc2 = 0; t2 = t + gridDim.x; }
                if (t2 < tiles) {
                    int m2 = t2 << 7, kb2 = kc2 << 6;
                    #pragma unroll
                    for (int j = 0; j < 8; j++) {
                        int idx = tid + (j << 8);
                        int gm = m2 + (idx >> 4); if (gm > M - 1) gm = M - 1;
                        pf[j] = *(const float4*)(A + (size_t)gm * K + kb2 + ((idx & 15) << 2));
                    }
                }
            }
            // ---- MMA over 4 k16-steps of this chunk
            const uint32_t abase = sbase + buf * A_BUF_B;
            #pragma unroll
            for (int ks = 0; ks < 4; ks++) {
                const int ka = ks << 4;
                uint32_t ah[4][4], al[4][4];
                #pragma unroll
                for (int mt = 0; mt < 4; mt++) {
                    uint32_t roff = ((uint32_t)(wm * 64 + mt * 16 + a_row) * 72
                                     + ka + a_k) * 2u;
                    ldsm_x4(abase + roff, ah[mt]);
                    ldsm_x4(abase + A_CH_B + roff, al[mt]);
                }
                uint32_t bh[4][2], bl[4][2];
                #pragma unroll
                for (int np = 0; np < 2; np++) {
                    uint32_t roff = ((uint32_t)(wn * 32 + np * 16 + b_row) * BS
                                     + kb + ka + b_k) * 2u;
                    uint32_t rh[4], rl[4];
                    ldsm_x4(sbase + B_BASE + roff, rh);
                    ldsm_x4(sbase + B_BASE + BB + roff, rl);
                    bh[np*2][0] = rh[0]; bh[np*2][1] = rh[1];
                    bh[np*2+1][0] = rh[2]; bh[np*2+1][1] = rh[3];
                    bl[np*2][0] = rl[0]; bl[np*2][1] = rl[1];
                    bl[np*2+1][0] = rl[2]; bl[np*2+1][1] = rl[3];
                }
                #pragma unroll
                for (int mt = 0; mt < 4; mt++)
                    #pragma unroll
                    for (int nt = 0; nt < 4; nt++) {
                        mma_bf16(acc[mt][nt], ah[mt], bh[nt]);
                        mma_bf16(acc[mt][nt], ah[mt], bl[nt]);
                        mma_bf16(acc[mt][nt], al[mt], bh[nt]);
                    }
            }
            buf ^= 1;
        }

        // ---- epilogue
        const int g  = lane >> 2;
        const int t2 = (lane & 3) << 1;
        #pragma unroll
        for (int mt = 0; mt < 4; mt++) {
            int r0 = m0 + wm * 64 + mt * 16 + g;
            #pragma unroll
            for (int nt = 0; nt < 4; nt++) {
                int c0 = wn * 32 + nt * 8 + t2;
                float2 bv = *(const float2*)(bias + c0);
                #pragma unroll
                for (int half = 0; half < 2; half++) {
                    int r = r0 + half * 8;
                    if (r >= M) continue;
                    size_t o = (size_t)r * Cld + c0;
                    float2 v = make_float2(acc[mt][nt][half*2]   + bv.x,
                                           acc[mt][nt][half*2+1] + bv.y);
                    if (res) {
                        float2 rv = *(const float2*)(res + o);
                        if (Rsc) {
                            float2 rs = *(const float2*)(Rsc + c0);
                            float2 rb = *(const float2*)(Rsh + c0);
                            rv.x = rv.x * rs.x + rb.x;
                            rv.y = rv.y * rs.y + rb.y;
                        }
                        v.x += rv.x; v.y += rv.y;
                    }
                    if (relu) { v.x = fmaxf(v.x, 0.f); v.y = fmaxf(v.y, 0.f); }
                    *(float2*)(C + o) = v;
                }
            }
        }
    }
}

// ---------------- edge kernel: score, e_attn (in place), s, segment sums ---
__global__ __launch_bounds__(256)
void k_edge(const int* __restrict__ src, const int* __restrict__ dst)
{
    const int t = threadIdx.x & 127;
    const int e = blockIdx.x * 2 + (threadIdx.x >> 7);
    if (e >= EG) return;
    const int s = src[e];
    const int d = dst[e];
    float sc = g_K[(size_t)s * 128 + t] * g_Q[(size_t)d * 128 + t] * 0.25f
             * g_EA[(size_t)e * 128 + t];
    g_EA[(size_t)e * 128 + t] = sc;
    float sum = sc;
    #pragma unroll
    for (int off = 8; off; off >>= 1)
        sum += __shfl_xor_sync(0xffffffffu, sum, off, 16);
    sum = fminf(fmaxf(sum, -5.f), 5.f);
    float ss = __expf(sum);
    atomicAdd(&g_wV[(size_t)d * 128 + t], g_V[(size_t)s * 128 + t] * ss);
    if ((t & 15) == 0)
        atomicAdd(&g_z[(size_t)d * 8 + (t >> 4)], ss);
}

// ---------------- h_attn = wV / (z + 1e-6) ----------------------------------
__global__ void k_hattn()
{
    size_t i = (size_t)blockIdx.x * blockDim.x + threadIdx.x;
    if (i >= (size_t)NN * 128) return;
    int c = (int)(i & 127);
    size_t n = i >> 7;
    g_HA[i] = g_wV[i] / (g_z[n * 8 + (c >> 4)] + 1e-6f);
}

// ---------------- batch-norm ------------------------------------------------
__global__ __launch_bounds__(256)
void k_bn_reduce(const float* __restrict__ X, int M, int slot)
{
    int c  = threadIdx.x & 127;
    int r0 = blockIdx.x * 2 + (threadIdx.x >> 7);
    double s = 0.0, q = 0.0;
    for (int r = r0; r < M; r += gridDim.x * 2) {
        float v = X[(size_t)r * 128 + c];
        s += v;
        q += (double)v * v;
    }
    atomicAdd(&g_sum[slot * 128 + c], s);
    atomicAdd(&g_sq [slot * 128 + c], q);
}

__global__ void k_bn_finalize(int slot, float Mf,
                              const float* __restrict__ g, const float* __restrict__ b)
{
    int c = threadIdx.x;
    double mu  = g_sum[slot * 128 + c] / (double)Mf;
    double var = g_sq [slot * 128 + c] / (double)Mf - mu * mu;
    float sc = g[c] * rsqrtf((float)var + 1e-5f);
    g_bnsc[slot * 128 + c] = sc;
    g_bnsh[slot * 128 + c] = b[c] - (float)mu * sc;
}

__global__ __launch_bounds__(256)
void k_bn_apply(float* __restrict__ X, size_t M, int slot)
{
    size_t total4 = M * 32;
    size_t i = (size_t)blockIdx.x * blockDim.x + threadIdx.x;
    size_t stride = (size_t)gridDim.x * blockDim.x;
    for (size_t j = i; j < total4; j += stride) {
        int c = (int)(j & 31) * 4;
        const float* sc = g_bnsc + slot * 128 + c;
        const float* sh = g_bnsh + slot * 128 + c;
        float4 v = ((float4*)X)[j];
        v.x = v.x * sc[0] + sh[0];
        v.y = v.y * sc[1] + sh[1];
        v.z = v.z * sc[2] + sh[2];
        v.w = v.w * sc[3] + sh[3];
        ((float4*)X)[j] = v;
    }
}

// ---------------- host orchestration ---------------------------------------
static void mm_gemm(const float* A, const float* W, const float* bias,
                    const float* res, float* C, int M, int K, int Nc, int relu,
                    const float* Asc = nullptr, const float* Ash = nullptr,
                    const float* Rsc = nullptr, const float* Rsh = nullptr)
{
    int tiles = (M + 127) / 128;
    int grid = tiles < 148 ? tiles : 148;
    if (K == 128) {
        size_t smem = B_BASE + 2 * 128 * (128 + 8) * 2;   // 143360
        if (Nc == 128) {
            k_mmgemm<2><<<grid, 256, smem>>>(A, W, bias, res, C, M, 128, 128, relu,
                                             Asc, Ash, Rsc, Rsh);
        } else { // Nc == 256: two column halves
            k_mmgemm<2><<<grid, 256, smem>>>(A, W, bias, res, C, M, 256, 256, relu,
                                             Asc, Ash, Rsc, Rsh);
            k_mmgemm<2><<<grid, 256, smem>>>(A, W + 128, bias + 128,
                                             res ? res + 128 : nullptr, C + 128,
                                             M, 256, 256, relu, Asc, Ash,
                                             Rsc ? Rsc + 128 : nullptr,
                                             Rsh ? Rsh + 128 : nullptr);
        }
    } else { // K == 256, Nc == 128
        size_t smem = B_BASE + 2 * 128 * (256 + 8) * 2;   // 208896
        k_mmgemm<4><<<grid, 256, smem>>>(A, W, bias, res, C, M, 128, 128, relu,
                                         Asc, Ash, Rsc, Rsh);
    }
}

extern "C" void kernel_launch(void* const* d_in, const int* in_sizes, int n_in,
                              void* d_out, int out_size)
{
    const float* h   = (const float*)d_in[0];
    const float* e   = (const float*)d_in[1];
    const int*   src = (const int*)d_in[2];
    const int*   dst = (const int*)d_in[3];
    const float* WQ  = (const float*)d_in[4];   const float* bQ  = (const float*)d_in[5];
    const float* WK  = (const float*)d_in[6];   const float* bK  = (const float*)d_in[7];
    const float* WV  = (const float*)d_in[8];   const float* bV  = (const float*)d_in[9];
    const float* WE  = (const float*)d_in[10];  const float* bE  = (const float*)d_in[11];
    const float* WOh = (const float*)d_in[12];  const float* bOh = (const float*)d_in[13];
    const float* WOe = (const float*)d_in[14];  const float* bOe = (const float*)d_in[15];
    const float* Wh1 = (const float*)d_in[16];  const float* bh1 = (const float*)d_in[17];
    const float* Wh2 = (const float*)d_in[18];  const float* bh2 = (const float*)d_in[19];
    const float* We1 = (const float*)d_in[20];  const float* be1 = (const float*)d_in[21];
    const float* We2 = (const float*)d_in[22];  const float* be2 = (const float*)d_in[23];
    const float* g1h = (const float*)d_in[24];
    const float* g1e = (const float*)d_in[25];
    const float* g2h = (const float*)d_in[26];
    const float* g2e = (const float*)d_in[27];
    const float* b1h = (const float*)d_in[28];
    const float* b1e = (const float*)d_in[29];
    const float* b2h = (const float*)d_in[30];
    const float* b2e = (const float*)d_in[31];

    float *pQ, *pK, *pV, *pHA, *ph1, *phidh, *pEA, *pe1, *phide, *pbnsc, *pbnsh;
    cudaGetSymbolAddress((void**)&pQ,    g_Q);
    cudaGetSymbolAddress((void**)&pK,    g_K);
    cudaGetSymbolAddress((void**)&pV,    g_V);
    cudaGetSymbolAddress((void**)&pHA,   g_HA);
    cudaGetSymbolAddress((void**)&ph1,   g_h1);
    cudaGetSymbolAddress((void**)&phidh, g_hidh);
    cudaGetSymbolAddress((void**)&pEA,   g_EA);
    cudaGetSymbolAddress((void**)&pe1,   g_e1);
    cudaGetSymbolAddress((void**)&phide, g_hide);
    cudaGetSymbolAddress((void**)&pbnsc, g_bnsc);
    cudaGetSymbolAddress((void**)&pbnsh, g_bnsh);

    cudaFuncSetAttribute(k_mmgemm<2>, cudaFuncAttributeMaxDynamicSharedMemorySize, 143360);
    cudaFuncSetAttribute(k_mmgemm<4>, cudaFuncAttributeMaxDynamicSharedMemorySize, 208896);

    float* out_h = (float*)d_out;                       // [NN,128]
    float* out_e = (float*)d_out + (size_t)NN * 128;    // [EG,128]

    // 0) zero accumulators + BN stats
    k_zero<<<4096, 256>>>();

    // 1) projections
    mm_gemm(h, WQ, bQ, nullptr, pQ,  NN, 128, 128, 0);
    mm_gemm(h, WK, bK, nullptr, pK,  NN, 128, 128, 0);
    mm_gemm(h, WV, bV, nullptr, pV,  NN, 128, 128, 0);
    mm_gemm(e, WE, bE, nullptr, pEA, EG, 128, 128, 0);

    // 2) edge scores + attention weights + segment sums (atomics)
    k_edge<<<EG / 2, 256>>>(src, dst);

    // 3) h_attn
    k_hattn<<<(NN * 128 + 255) / 256, 256>>>();

    // 4) O projections with residual
    mm_gemm(pHA, WOh, bOh, h, ph1, NN, 128, 128, 0);
    mm_gemm(pEA, WOe, bOe, e, pe1, EG, 128, 128, 0);

    // 5) BN #1 stats (apply is fused into the FFN GEMMs below)
    k_bn_reduce<<<1024, 256>>>(ph1, NN, 0);
    k_bn_finalize<<<1, 128>>>(0, (float)NN, g1h, b1h);
    k_bn_reduce<<<2048, 256>>>(pe1, EG, 1);
    k_bn_finalize<<<1, 128>>>(1, (float)EG, g1e, b1e);

    // 6) FFNs: A-side BN fused into FFN1, res-side BN fused into FFN2
    mm_gemm(ph1,   Wh1, bh1, nullptr, phidh, NN, 128, 256, 1,
            pbnsc + 0 * 128, pbnsh + 0 * 128);
    mm_gemm(phidh, Wh2, bh2, ph1,     out_h, NN, 256, 128, 0,
            nullptr, nullptr, pbnsc + 0 * 128, pbnsh + 0 * 128);
    mm_gemm(pe1,   We1, be1, nullptr, phide, EG, 128, 256, 1,
            pbnsc + 1 * 128, pbnsh + 1 * 128);
    mm_gemm(phide, We2, be2, pe1,     out_e, EG, 256, 128, 0,
            nullptr, nullptr, pbnsc + 1 * 128, pbnsh + 1 * 128);

    // 7) BN #2 (in place on the output buffer)
    k_bn_reduce<<<1024, 256>>>(out_h, NN, 2);
    k_bn_finalize<<<1, 128>>>(2, (float)NN, g2h, b2h);
    k_bn_apply<<<12800, 256>>>(out_h, (size_t)NN, 2);
    k_bn_reduce<<<2048, 256>>>(out_e, EG, 3);
    k_bn_finalize<<<1, 128>>>(3, (float)EG, g2e, b2e);
    k_bn_apply<<<100000, 256>>>(out_e, (size_t)EG, 3);
}

// round 5
// speedup vs baseline: 1.6799x; 1.0275x over previous
#include <cuda_runtime.h>
#include <cuda_bf16.h>
#include <cstdint>
#include <math.h>

// Problem constants
#define NN 50000
#define EG 800000
// DIM = 128, H = 8, HD = 16

// ---------------- scratch (device globals; no runtime allocation) ----------
__device__ float  g_Q   [(size_t)NN * 128];
__device__ float  g_K   [(size_t)NN * 128];
__device__ float  g_V   [(size_t)NN * 128];
__device__ float  g_HA  [(size_t)NN * 128];   // h_attn
__device__ float  g_h1  [(size_t)NN * 128];
__device__ float  g_hidh[(size_t)NN * 256];
__device__ float  g_wV  [(size_t)NN * 128];
__device__ float  g_z   [(size_t)NN * 8];
__device__ float  g_EA  [(size_t)EG * 128];   // Ee, overwritten in-place with e_attn
__device__ float  g_e1  [(size_t)EG * 128];
__device__ float  g_hide[(size_t)EG * 256];
__device__ double g_sum [4 * 128];
__device__ double g_sq  [4 * 128];
__device__ float  g_bnsc[4 * 128];
__device__ float  g_bnsh[4 * 128];
__device__ float  g_zerobias[128];            // static zeros (never written)

// ---------------- zero accumulators ----------------------------------------
__global__ void k_zero() {
    size_t i = (size_t)blockIdx.x * blockDim.x + threadIdx.x;
    size_t stride = (size_t)gridDim.x * blockDim.x;
    for (size_t j = i; j < (size_t)NN * 128; j += stride) g_wV[j] = 0.f;
    for (size_t j = i; j < (size_t)NN * 8;   j += stride) g_z[j]  = 0.f;
    if (i < 512) { g_sum[i] = 0.0; g_sq[i] = 0.0; }
}

// ============================================================================
// mma.sync bf16 helpers (family-portable PTX)
// ============================================================================
__device__ __forceinline__ uint32_t smem_u32(const void* p) {
    uint32_t a;
    asm("{ .reg .u64 t; cvta.to.shared.u64 t, %1; cvt.u32.u64 %0, t; }"
        : "=r"(a) : "l"(p));
    return a;
}

__device__ __forceinline__ void ldsm_x4(uint32_t addr, uint32_t* r) {
    asm volatile("ldmatrix.sync.aligned.m8n8.x4.shared.b16 {%0,%1,%2,%3}, [%4];"
        : "=r"(r[0]), "=r"(r[1]), "=r"(r[2]), "=r"(r[3]) : "r"(addr));
}

__device__ __forceinline__ void mma_bf16(float* acc, const uint32_t* a, const uint32_t* b) {
    asm volatile(
        "mma.sync.aligned.m16n8k16.row.col.f32.bf16.bf16.f32 "
        "{%0,%1,%2,%3},{%4,%5,%6,%7},{%8,%9},{%0,%1,%2,%3};"
        : "+f"(acc[0]), "+f"(acc[1]), "+f"(acc[2]), "+f"(acc[3])
        : "r"(a[0]), "r"(a[1]), "r"(a[2]), "r"(a[3]), "r"(b[0]), "r"(b[1]));
}

__device__ __forceinline__ void split_pair(float x0, float x1, uint32_t& hi, uint32_t& lo)
{
    __nv_bfloat162 h = __floats2bfloat162_rn(x0, x1);
    float r0 = x0 - __bfloat162float(__low2bfloat16(h));
    float r1 = x1 - __bfloat162float(__high2bfloat16(h));
    __nv_bfloat162 l = __floats2bfloat162_rn(r0, r1);
    hi = *reinterpret_cast<uint32_t*>(&h);
    lo = *reinterpret_cast<uint32_t*>(&l);
}

// ============================================================================
// Pipelined HMMA bf16 3-split GEMM, K = 128 fixed, N-tile = 128 columns.
//   C[:, :128] = [resOp(res) +] Aop(A[:, :128]) @ W[:128, :128] + bias (, relu)
// A leading dim Ald, W leading dim Wld, C/res leading dim Cld.
// Optional per-k affine on A (Asc/Ash) and per-col affine on res (Rsc/Rsh).
//
// 256 threads = 8 warps (2 wm x 4 wn), warp tile 64x32, M-tile 128.
// A double-buffered bf16 hi/lo, k-chunks of 32, register prefetch.
// SMEM: A: 2 bufs x (hi+lo) x [128][40] bf16 = 40960 B
//       B: (hi+lo) x [128][136] bf16          = 69632 B   total 110592 B
// => 2 CTAs per SM.
// ============================================================================
#define A_CH_B 10240
#define A_BUF_B 20480
#define B_BASE 40960
#define BB 34816u

__global__ __launch_bounds__(256, 2)
void k_mmgemm(const float* __restrict__ A, int Ald,
              const float* __restrict__ W, int Wld,
              const float* __restrict__ bias, const float* __restrict__ res,
              float* __restrict__ C, int Cld, int M, int relu,
              const float* __restrict__ Asc, const float* __restrict__ Ash,
              const float* __restrict__ Rsc, const float* __restrict__ Rsh)
{
    extern __shared__ char smem[];
    const uint32_t sbase = smem_u32(smem);

    const int tid  = threadIdx.x;
    const int lane = tid & 31;
    const int wid  = tid >> 5;
    const int wm   = wid >> 2;          // 0..1
    const int wn   = wid & 3;           // 0..3

    // ---- load W[0:128, 0:128] once: fp32 -> bf16 hi/lo at [n][k], BS=136
    {
        #pragma unroll
        for (int i = tid; i < 32 * 128; i += 256) {
            int n  = i & 127;
            int k4 = (i >> 7) << 2;
            const float* wp = W + (size_t)k4 * Wld + n;
            float x0 = wp[0];
            float x1 = wp[Wld];
            float x2 = wp[2 * Wld];
            float x3 = wp[3 * Wld];
            uint32_t h01, l01, h23, l23;
            split_pair(x0, x1, h01, l01);
            split_pair(x2, x3, h23, l23);
            uint32_t off = ((uint32_t)n * 136 + k4) * 2u;
            *(uint2*)(smem + B_BASE + off)      = make_uint2(h01, h23);
            *(uint2*)(smem + B_BASE + BB + off) = make_uint2(l01, l23);
        }
    }

    const int tiles = (M + 127) >> 7;

    // ldmatrix lane-address components
    const int a_row = (lane & 15);
    const int a_k   = (lane >> 4) << 3;
    const int b_row = (lane & 7) + ((lane >> 4) << 3);
    const int b_k   = ((lane >> 3) & 1) << 3;

    // prefetch chunk 0 of first tile: 128 rows x 32 cols fp32 = 1024 float4
    float4 pf[4];
    int t = blockIdx.x;
    if (t < tiles) {
        int m0 = t << 7;
        #pragma unroll
        for (int j = 0; j < 4; j++) {
            int idx = tid + (j << 8);
            int gm = m0 + (idx >> 3); if (gm > M - 1) gm = M - 1;
            pf[j] = *(const float4*)(A + (size_t)gm * Ald + ((idx & 7) << 2));
        }
    }
    int buf = 0;

    for (; t < tiles; t += gridDim.x) {
        const int m0 = t << 7;
        float acc[4][4][4] = {};
        #pragma unroll
        for (int kc = 0; kc < 4; kc++) {
            const int kb = kc << 5;
            // ---- convert + store prefetched chunk into buf
            {
                char* ah_base = smem + buf * A_BUF_B;
                #pragma unroll
                for (int j = 0; j < 4; j++) {
                    int idx = tid + (j << 8);
                    int row = idx >> 3;
                    int c4  = (idx & 7) << 2;
                    float4 v = pf[j];
                    if (Asc) {
                        float4 sc = *(const float4*)(Asc + kb + c4);
                        float4 sh = *(const float4*)(Ash + kb + c4);
                        v.x = v.x * sc.x + sh.x;
                        v.y = v.y * sc.y + sh.y;
                        v.z = v.z * sc.z + sh.z;
                        v.w = v.w * sc.w + sh.w;
                    }
                    uint32_t h01, l01, h23, l23;
                    split_pair(v.x, v.y, h01, l01);
                    split_pair(v.z, v.w, h23, l23);
                    uint32_t off = ((uint32_t)row * 40 + c4) * 2u;
                    *(uint2*)(ah_base + off)          = make_uint2(h01, h23);
                    *(uint2*)(ah_base + A_CH_B + off) = make_uint2(l01, l23);
                }
            }
            __syncthreads();
            // ---- prefetch next chunk (overlaps with MMA below)
            {
                int kc2 = kc + 1, t2 = t;
                if (kc2 == 4) { kc2 = 0; t2 = t + gridDim.x; }
                if (t2 < tiles) {
                    int m2 = t2 << 7, kb2 = kc2 << 5;
                    #pragma unroll
                    for (int j = 0; j < 4; j++) {
                        int idx = tid + (j << 8);
                        int gm = m2 + (idx >> 3); if (gm > M - 1) gm = M - 1;
                        pf[j] = *(const float4*)(A + (size_t)gm * Ald + kb2 + ((idx & 7) << 2));
                    }
                }
            }
            // ---- MMA over 2 k16-steps of this chunk
            const uint32_t abase = sbase + buf * A_BUF_B;
            #pragma unroll
            for (int ks = 0; ks < 2; ks++) {
                const int ka = ks << 4;
                uint32_t ah[4][4], al[4][4];
                #pragma unroll
                for (int mt = 0; mt < 4; mt++) {
                    uint32_t roff = ((uint32_t)(wm * 64 + mt * 16 + a_row) * 40
                                     + ka + a_k) * 2u;
                    ldsm_x4(abase + roff, ah[mt]);
                    ldsm_x4(abase + A_CH_B + roff, al[mt]);
                }
                uint32_t bh[4][2], bl[4][2];
                #pragma unroll
                for (int np = 0; np < 2; np++) {
                    uint32_t roff = ((uint32_t)(wn * 32 + np * 16 + b_row) * 136
                                     + kb + ka + b_k) * 2u;
                    uint32_t rh[4], rl[4];
                    ldsm_x4(sbase + B_BASE + roff, rh);
                    ldsm_x4(sbase + B_BASE + BB + roff, rl);
                    bh[np*2][0] = rh[0]; bh[np*2][1] = rh[1];
                    bh[np*2+1][0] = rh[2]; bh[np*2+1][1] = rh[3];
                    bl[np*2][0] = rl[0]; bl[np*2][1] = rl[1];
                    bl[np*2+1][0] = rl[2]; bl[np*2+1][1] = rl[3];
                }
                #pragma unroll
                for (int mt = 0; mt < 4; mt++)
                    #pragma unroll
                    for (int nt = 0; nt < 4; nt++) {
                        mma_bf16(acc[mt][nt], ah[mt], bh[nt]);
                        mma_bf16(acc[mt][nt], ah[mt], bl[nt]);
                        mma_bf16(acc[mt][nt], al[mt], bh[nt]);
                    }
            }
            buf ^= 1;
        }

        // ---- epilogue
        const int g  = lane >> 2;
        const int t2 = (lane & 3) << 1;
        #pragma unroll
        for (int mt = 0; mt < 4; mt++) {
            int r0 = m0 + wm * 64 + mt * 16 + g;
            #pragma unroll
            for (int nt = 0; nt < 4; nt++) {
                int c0 = wn * 32 + nt * 8 + t2;
                float2 bv = *(const float2*)(bias + c0);
                #pragma unroll
                for (int half = 0; half < 2; half++) {
                    int r = r0 + half * 8;
                    if (r >= M) continue;
                    size_t o = (size_t)r * Cld + c0;
                    float2 v = make_float2(acc[mt][nt][half*2]   + bv.x,
                                           acc[mt][nt][half*2+1] + bv.y);
                    if (res) {
                        float2 rv = *(const float2*)(res + o);
                        if (Rsc) {
                            float2 rs = *(const float2*)(Rsc + c0);
                            float2 rb = *(const float2*)(Rsh + c0);
                            rv.x = rv.x * rs.x + rb.x;
                            rv.y = rv.y * rs.y + rb.y;
                        }
                        v.x += rv.x; v.y += rv.y;
                    }
                    if (relu) { v.x = fmaxf(v.x, 0.f); v.y = fmaxf(v.y, 0.f); }
                    *(float2*)(C + o) = v;
                }
            }
        }
    }
}

// ---------------- edge kernel: score, e_attn (in place), s, segment sums ---
__global__ __launch_bounds__(256)
void k_edge(const int* __restrict__ src, const int* __restrict__ dst)
{
    const int t = threadIdx.x & 127;
    const int e = blockIdx.x * 2 + (threadIdx.x >> 7);
    if (e >= EG) return;
    const int s = src[e];
    const int d = dst[e];
    float sc = g_K[(size_t)s * 128 + t] * g_Q[(size_t)d * 128 + t] * 0.25f
             * g_EA[(size_t)e * 128 + t];
    g_EA[(size_t)e * 128 + t] = sc;
    float sum = sc;
    #pragma unroll
    for (int off = 8; off; off >>= 1)
        sum += __shfl_xor_sync(0xffffffffu, sum, off, 16);
    sum = fminf(fmaxf(sum, -5.f), 5.f);
    float ss = __expf(sum);
    atomicAdd(&g_wV[(size_t)d * 128 + t], g_V[(size_t)s * 128 + t] * ss);
    if ((t & 15) == 0)
        atomicAdd(&g_z[(size_t)d * 8 + (t >> 4)], ss);
}

// ---------------- h_attn = wV / (z + 1e-6) ----------------------------------
__global__ void k_hattn()
{
    size_t i = (size_t)blockIdx.x * blockDim.x + threadIdx.x;
    if (i >= (size_t)NN * 128) return;
    int c = (int)(i & 127);
    size_t n = i >> 7;
    g_HA[i] = g_wV[i] / (g_z[n * 8 + (c >> 4)] + 1e-6f);
}

// ---------------- batch-norm ------------------------------------------------
__global__ __launch_bounds__(256)
void k_bn_reduce(const float* __restrict__ X, int M, int slot)
{
    int c  = threadIdx.x & 127;
    int r0 = blockIdx.x * 2 + (threadIdx.x >> 7);
    double s = 0.0, q = 0.0;
    for (int r = r0; r < M; r += gridDim.x * 2) {
        float v = X[(size_t)r * 128 + c];
        s += v;
        q += (double)v * v;
    }
    atomicAdd(&g_sum[slot * 128 + c], s);
    atomicAdd(&g_sq [slot * 128 + c], q);
}

__global__ void k_bn_finalize(int slot, float Mf,
                              const float* __restrict__ g, const float* __restrict__ b)
{
    int c = threadIdx.x;
    double mu  = g_sum[slot * 128 + c] / (double)Mf;
    double var = g_sq [slot * 128 + c] / (double)Mf - mu * mu;
    float sc = g[c] * rsqrtf((float)var + 1e-5f);
    g_bnsc[slot * 128 + c] = sc;
    g_bnsh[slot * 128 + c] = b[c] - (float)mu * sc;
}

__global__ __launch_bounds__(256)
void k_bn_apply(float* __restrict__ X, size_t M, int slot)
{
    size_t total4 = M * 32;
    size_t i = (size_t)blockIdx.x * blockDim.x + threadIdx.x;
    size_t stride = (size_t)gridDim.x * blockDim.x;
    for (size_t j = i; j < total4; j += stride) {
        int c = (int)(j & 31) * 4;
        const float* sc = g_bnsc + slot * 128 + c;
        const float* sh = g_bnsh + slot * 128 + c;
        float4 v = ((float4*)X)[j];
        v.x = v.x * sc[0] + sh[0];
        v.y = v.y * sc[1] + sh[1];
        v.z = v.z * sc[2] + sh[2];
        v.w = v.w * sc[3] + sh[3];
        ((float4*)X)[j] = v;
    }
}

// ---------------- host orchestration ---------------------------------------
#define GEMM_SMEM 110592

static void mm128(const float* A, int Ald, const float* W, int Wld,
                  const float* bias, const float* res, float* C, int Cld,
                  int M, int relu,
                  const float* Asc = nullptr, const float* Ash = nullptr,
                  const float* Rsc = nullptr, const float* Rsh = nullptr)
{
    int tiles = (M + 127) / 128;
    int grid = tiles < 296 ? tiles : 296;
    k_mmgemm<<<grid, 256, GEMM_SMEM>>>(A, Ald, W, Wld, bias, res, C, Cld, M, relu,
                                       Asc, Ash, Rsc, Rsh);
}

extern "C" void kernel_launch(void* const* d_in, const int* in_sizes, int n_in,
                              void* d_out, int out_size)
{
    const float* h   = (const float*)d_in[0];
    const float* e   = (const float*)d_in[1];
    const int*   src = (const int*)d_in[2];
    const int*   dst = (const int*)d_in[3];
    const float* WQ  = (const float*)d_in[4];   const float* bQ  = (const float*)d_in[5];
    const float* WK  = (const float*)d_in[6];   const float* bK  = (const float*)d_in[7];
    const float* WV  = (const float*)d_in[8];   const float* bV  = (const float*)d_in[9];
    const float* WE  = (const float*)d_in[10];  const float* bE  = (const float*)d_in[11];
    const float* WOh = (const float*)d_in[12];  const float* bOh = (const float*)d_in[13];
    const float* WOe = (const float*)d_in[14];  const float* bOe = (const float*)d_in[15];
    const float* Wh1 = (const float*)d_in[16];  const float* bh1 = (const float*)d_in[17];
    const float* Wh2 = (const float*)d_in[18];  const float* bh2 = (const float*)d_in[19];
    const float* We1 = (const float*)d_in[20];  const float* be1 = (const float*)d_in[21];
    const float* We2 = (const float*)d_in[22];  const float* be2 = (const float*)d_in[23];
    const float* g1h = (const float*)d_in[24];
    const float* g1e = (const float*)d_in[25];
    const float* g2h = (const float*)d_in[26];
    const float* g2e = (const float*)d_in[27];
    const float* b1h = (const float*)d_in[28];
    const float* b1e = (const float*)d_in[29];
    const float* b2h = (const float*)d_in[30];
    const float* b2e = (const float*)d_in[31];

    float *pQ, *pK, *pV, *pHA, *ph1, *phidh, *pEA, *pe1, *phide, *pbnsc, *pbnsh, *pzb;
    cudaGetSymbolAddress((void**)&pQ,    g_Q);
    cudaGetSymbolAddress((void**)&pK,    g_K);
    cudaGetSymbolAddress((void**)&pV,    g_V);
    cudaGetSymbolAddress((void**)&pHA,   g_HA);
    cudaGetSymbolAddress((void**)&ph1,   g_h1);
    cudaGetSymbolAddress((void**)&phidh, g_hidh);
    cudaGetSymbolAddress((void**)&pEA,   g_EA);
    cudaGetSymbolAddress((void**)&pe1,   g_e1);
    cudaGetSymbolAddress((void**)&phide, g_hide);
    cudaGetSymbolAddress((void**)&pbnsc, g_bnsc);
    cudaGetSymbolAddress((void**)&pbnsh, g_bnsh);
    cudaGetSymbolAddress((void**)&pzb,   g_zerobias);

    cudaFuncSetAttribute(k_mmgemm, cudaFuncAttributeMaxDynamicSharedMemorySize, GEMM_SMEM);

    float* out_h = (float*)d_out;                       // [NN,128]
    float* out_e = (float*)d_out + (size_t)NN * 128;    // [EG,128]

    // 0) zero accumulators + BN stats
    k_zero<<<4096, 256>>>();

    // 1) projections
    mm128(h, 128, WQ, 128, bQ, nullptr, pQ,  128, NN, 0);
    mm128(h, 128, WK, 128, bK, nullptr, pK,  128, NN, 0);
    mm128(h, 128, WV, 128, bV, nullptr, pV,  128, NN, 0);
    mm128(e, 128, WE, 128, bE, nullptr, pEA, 128, EG, 0);

    // 2) edge scores + attention weights + segment sums (atomics)
    k_edge<<<EG / 2, 256>>>(src, dst);

    // 3) h_attn
    k_hattn<<<(NN * 128 + 255) / 256, 256>>>();

    // 4) O projections with residual
    mm128(pHA, 128, WOh, 128, bOh, h, ph1, 128, NN, 0);
    mm128(pEA, 128, WOe, 128, bOe, e, pe1, 128, EG, 0);

    // 5) BN #1 stats (apply fused into FFN GEMMs)
    k_bn_reduce<<<1024, 256>>>(ph1, NN, 0);
    k_bn_finalize<<<1, 128>>>(0, (float)NN, g1h, b1h);
    k_bn_reduce<<<2048, 256>>>(pe1, EG, 1);
    k_bn_finalize<<<1, 128>>>(1, (float)EG, g1e, b1e);

    // 6) FFNs. FFN1: Nc=256 as two column halves, A-side BN fused.
    //    FFN2: K=256 as two K=128 accumulation passes, res-side BN fused in pass1.
    // h-side
    mm128(ph1, 128, Wh1,       256, bh1,       nullptr, phidh,       256, NN, 1,
          pbnsc + 0, pbnsh + 0);
    mm128(ph1, 128, Wh1 + 128, 256, bh1 + 128, nullptr, phidh + 128, 256, NN, 1,
          pbnsc + 0, pbnsh + 0);
    mm128(phidh,       256, Wh2,             128, bh2, ph1,   out_h, 128, NN, 0,
          nullptr, nullptr, pbnsc + 0, pbnsh + 0);
    mm128(phidh + 128, 256, Wh2 + 128 * 128, 128, pzb, out_h, out_h, 128, NN, 0);
    // e-side
    mm128(pe1, 128, We1,       256, be1,       nullptr, phide,       256, EG, 1,
          pbnsc + 128, pbnsh + 128);
    mm128(pe1, 128, We1 + 128, 256, be1 + 128, nullptr, phide + 128, 256, EG, 1,
          pbnsc + 128, pbnsh + 128);
    mm128(phide,       256, We2,             128, be2, pe1,   out_e, 128, EG, 0,
          nullptr, nullptr, pbnsc + 128, pbnsh + 128);
    mm128(phide + 128, 256, We2 + 128 * 128, 128, pzb, out_e, out_e, 128, EG, 0);

    // 7) BN #2 (in place on the output buffer)
    k_bn_reduce<<<1024, 256>>>(out_h, NN, 2);
    k_bn_finalize<<<1, 128>>>(2, (float)NN, g2h, b2h);
    k_bn_apply<<<12800, 256>>>(out_h, (size_t)NN, 2);
    k_bn_reduce<<<2048, 256>>>(out_e, EG, 3);
    k_bn_finalize<<<1, 128>>>(3, (float)EG, g2e, b2e);
    k_bn_apply<<<100000, 256>>>(out_e, (size_t)EG, 3);
}